// round 1
// baseline (speedup 1.0000x reference)
#include <cuda_runtime.h>

#define NATOMS 10000
#define NNBH   48
#define NIN    128
#define NF     128
#define NOUT   128
#define NG     25
#define RCUT   5.0f
#define LN2F   0.69314718055994531f

// scratch (allocation-free rule: device globals)
__device__ float g_ybuf[NATOMS * NF];
__device__ float g_acc [NATOMS * NF];

__device__ __forceinline__ float sspf(float v) {
    // shifted softplus: log(1+exp(v)) - log(2), numerically stable
    float e  = __expf(-fabsf(v));
    float sp = fmaxf(v, 0.0f) + __logf(1.0f + e);
    return sp - LN2F;
}

// ---------------------------------------------------------------------------
// Kernel A/C: 64x128 tile GEMM, depth 128. micro-tile 4x8, 256 threads.
//   mode 0: out = X @ W              (kernel A: in2f)
//   mode 1: out = ssp(X @ W + bias)  (kernel C: f2out)
// dynamic smem: sW[128*128] + sX[64*128] = 98304 B
// ---------------------------------------------------------------------------
__global__ __launch_bounds__(256) void gemm128_kernel(
    const float* __restrict__ X, const float* __restrict__ W,
    const float* __restrict__ bias, float* __restrict__ out, int mode)
{
    extern __shared__ float smem[];
    float* sW = smem;            // 16384 floats
    float* sX = smem + 16384;    // 8192 floats

    int tid = threadIdx.x;
    // load W (128x128) fully
    const float4* Wv = (const float4*)W;
    float4* sWv = (float4*)sW;
    #pragma unroll
    for (int i = 0; i < 16; i++) sWv[tid + i * 256] = Wv[tid + i * 256];

    int row0 = blockIdx.x * 64;
    const float4* Xv = (const float4*)X;
    float4* sXv = (float4*)sX;
    #pragma unroll
    for (int i = 0; i < 8; i++) {
        int idx = tid + i * 256;        // float4 index into 64x32
        int r = idx >> 5, c4 = idx & 31;
        float4 v = make_float4(0.f, 0.f, 0.f, 0.f);
        if (row0 + r < NATOMS) v = Xv[(size_t)(row0 + r) * 32 + c4];
        sXv[idx] = v;
    }
    __syncthreads();

    int tr = tid >> 4, tc = tid & 15;
    int r0 = tr * 4, c0 = tc * 8;
    float acc[4][8];
    #pragma unroll
    for (int i = 0; i < 4; i++)
        #pragma unroll
        for (int c = 0; c < 8; c++) acc[i][c] = 0.f;

    #pragma unroll 4
    for (int j = 0; j < NIN; j++) {
        float a0 = sX[(r0 + 0) * NIN + j];
        float a1 = sX[(r0 + 1) * NIN + j];
        float a2 = sX[(r0 + 2) * NIN + j];
        float a3 = sX[(r0 + 3) * NIN + j];
        float4 w0 = *(float4*)&sW[j * NF + c0];
        float4 w1 = *(float4*)&sW[j * NF + c0 + 4];
        float wv[8] = {w0.x, w0.y, w0.z, w0.w, w1.x, w1.y, w1.z, w1.w};
        #pragma unroll
        for (int c = 0; c < 8; c++) {
            acc[0][c] += a0 * wv[c];
            acc[1][c] += a1 * wv[c];
            acc[2][c] += a2 * wv[c];
            acc[3][c] += a3 * wv[c];
        }
    }

    float bb[8];
    if (mode == 1) {
        #pragma unroll
        for (int c = 0; c < 8; c++) bb[c] = bias[c0 + c];
    }
    #pragma unroll
    for (int i = 0; i < 4; i++) {
        int r = row0 + r0 + i;
        if (r < NATOMS) {
            float o[8];
            #pragma unroll
            for (int c = 0; c < 8; c++) {
                o[c] = acc[i][c];
                if (mode == 1) o[c] = sspf(o[c] + bb[c]);
            }
            *(float4*)&out[(size_t)r * NF + c0]     = make_float4(o[0], o[1], o[2], o[3]);
            *(float4*)&out[(size_t)r * NF + c0 + 4] = make_float4(o[4], o[5], o[6], o[7]);
        }
    }
}

// ---------------------------------------------------------------------------
// Kernel B: fused filter-network + cutoff + gather + K-reduction.
// One atom per loop iteration; 256 threads; micro-tile 3x8 over [48,128].
// smem: W2(16384) W1(3200) H(6144) G(1200) Red(2048) CM(48) + Idx(48 int)
//       = 116288 B dynamic
// ---------------------------------------------------------------------------
#define GRID_B 1216

__global__ __launch_bounds__(256, 1) void cfconv_main_kernel(
    const float* __restrict__ dR,   const float* __restrict__ dRe,
    const float* __restrict__ pmask,const int*   __restrict__ nbr,
    const float* __restrict__ W1,   const float* __restrict__ b1,
    const float* __restrict__ W2,   const float* __restrict__ b2)
{
    extern __shared__ float smem[];
    float* sW2  = smem;                 // 16384
    float* sW1  = sW2 + 16384;          // 3200
    float* sH   = sW1 + 3200;           // 48*128 = 6144 (row-major [k][f])
    float* sG   = sH  + 6144;           // 48*25  = 1200 (row-major [k][g])
    float* sRed = sG  + 1200;           // 16*128 = 2048
    float* sCM  = sRed + 2048;          // 48
    int*   sIdx = (int*)(sCM + 48);     // 48

    int tid = threadIdx.x;

    // one-time weight load (L2-resident, cheap)
    #pragma unroll
    for (int i = tid; i < NG * NF; i += 256) sW1[i] = W1[i];
    {
        const float4* w2v = (const float4*)W2;
        float4* sw2v = (float4*)sW2;
        #pragma unroll
        for (int i = 0; i < 16; i++) sw2v[tid + i * 256] = w2v[tid + i * 256];
    }

    int tr = tid >> 4, tc = tid & 15;
    int r0 = tr * 3, c0 = tc * 8;
    float b1r[8], b2r[8];
    #pragma unroll
    for (int c = 0; c < 8; c++) { b1r[c] = b1[c0 + c]; b2r[c] = b2[c0 + c]; }

    for (int atom = blockIdx.x; atom < NATOMS; atom += GRID_B) {
        __syncthreads();  // A: previous iteration fully consumed shared state

        // stage per-atom inputs
        const float* gsrc = dRe + (size_t)atom * (NNBH * NG);
        #pragma unroll
        for (int i = tid; i < NNBH * NG; i += 256) sG[i] = gsrc[i];
        if (tid < NNBH) {
            sIdx[tid] = nbr[(size_t)atom * NNBH + tid];
            float d = dR[(size_t)atom * NNBH + tid];
            sCM[tid] = (d <= RCUT ? 1.0f : 0.0f) * pmask[(size_t)atom * NNBH + tid];
        }
        __syncthreads();  // B: inputs visible

        // GEMM1: H = ssp(G @ W1 + b1), [48,25]x[25,128]
        float h[3][8];
        #pragma unroll
        for (int i = 0; i < 3; i++)
            #pragma unroll
            for (int c = 0; c < 8; c++) h[i][c] = b1r[c];
        #pragma unroll
        for (int g = 0; g < NG; g++) {
            float a0 = sG[(r0 + 0) * NG + g];
            float a1 = sG[(r0 + 1) * NG + g];
            float a2 = sG[(r0 + 2) * NG + g];
            float4 w0 = *(float4*)&sW1[g * NF + c0];
            float4 w1 = *(float4*)&sW1[g * NF + c0 + 4];
            float wv[8] = {w0.x, w0.y, w0.z, w0.w, w1.x, w1.y, w1.z, w1.w};
            #pragma unroll
            for (int c = 0; c < 8; c++) {
                h[0][c] += a0 * wv[c];
                h[1][c] += a1 * wv[c];
                h[2][c] += a2 * wv[c];
            }
        }
        #pragma unroll
        for (int i = 0; i < 3; i++)
            #pragma unroll
            for (int c = 0; c < 8; c++)
                sH[(r0 + i) * NF + (c0 + c)] = sspf(h[i][c]);
        __syncthreads();  // C: H visible

        // GEMM2: P = H @ W2 + b2, [48,128]x[128,128]
        float acc[3][8];
        #pragma unroll
        for (int i = 0; i < 3; i++)
            #pragma unroll
            for (int c = 0; c < 8; c++) acc[i][c] = b2r[c];
        #pragma unroll 4
        for (int j = 0; j < NF; j++) {
            float a0 = sH[(r0 + 0) * NF + j];
            float a1 = sH[(r0 + 1) * NF + j];
            float a2 = sH[(r0 + 2) * NF + j];
            float4 w0 = *(float4*)&sW2[j * NF + c0];
            float4 w1 = *(float4*)&sW2[j * NF + c0 + 4];
            float wv[8] = {w0.x, w0.y, w0.z, w0.w, w1.x, w1.y, w1.z, w1.w};
            #pragma unroll
            for (int c = 0; c < 8; c++) {
                acc[0][c] += a0 * wv[c];
                acc[1][c] += a1 * wv[c];
                acc[2][c] += a2 * wv[c];
            }
        }

        // epilogue: cutoff*mask, gather y[idx], partial reduce over this thread's rows
        float part[8];
        #pragma unroll
        for (int c = 0; c < 8; c++) part[c] = 0.f;
        #pragma unroll
        for (int i = 0; i < 3; i++) {
            int k = r0 + i;
            float cm = sCM[k];
            const float* yrow = g_ybuf + (size_t)sIdx[k] * NF + c0;
            float4 y0 = *(const float4*)yrow;
            float4 y1 = *(const float4*)(yrow + 4);
            float yv[8] = {y0.x, y0.y, y0.z, y0.w, y1.x, y1.y, y1.z, y1.w};
            #pragma unroll
            for (int c = 0; c < 8; c++)
                part[c] += cm * acc[i][c] * yv[c];
        }
        *(float4*)&sRed[tr * NF + c0]     = make_float4(part[0], part[1], part[2], part[3]);
        *(float4*)&sRed[tr * NF + c0 + 4] = make_float4(part[4], part[5], part[6], part[7]);
        __syncthreads();  // D: partials visible

        if (tid < NF) {
            float s = 0.f;
            #pragma unroll
            for (int t = 0; t < 16; t++) s += sRed[t * NF + tid];
            g_acc[(size_t)atom * NF + tid] = s;
        }
    }
}

// ---------------------------------------------------------------------------
extern "C" void kernel_launch(void* const* d_in, const int* in_sizes, int n_in,
                              void* d_out, int out_size)
{
    const float* x       = (const float*)d_in[0];
    const float* dR      = (const float*)d_in[1];
    const float* dRe     = (const float*)d_in[2];
    const float* pmask   = (const float*)d_in[3];
    const int*   nbr     = (const int*)  d_in[4];
    const float* W1      = (const float*)d_in[5];
    const float* b1      = (const float*)d_in[6];
    const float* W2      = (const float*)d_in[7];
    const float* b2      = (const float*)d_in[8];
    const float* W_in2f  = (const float*)d_in[9];
    const float* W_f2out = (const float*)d_in[10];
    const float* b_f2out = (const float*)d_in[11];
    float* out = (float*)d_out;

    const int SMEM_AC = (16384 + 64 * 128) * 4;   // 98304 B
    const int SMEM_B  = (16384 + 3200 + 6144 + 1200 + 2048 + 48) * 4 + 48 * 4; // 116288 B

    cudaFuncSetAttribute(gemm128_kernel,     cudaFuncAttributeMaxDynamicSharedMemorySize, SMEM_AC);
    cudaFuncSetAttribute(cfconv_main_kernel, cudaFuncAttributeMaxDynamicSharedMemorySize, SMEM_B);

    float* ybuf; cudaGetSymbolAddress((void**)&ybuf, g_ybuf);
    float* accb; cudaGetSymbolAddress((void**)&accb, g_acc);

    int gridAC = (NATOMS + 63) / 64;  // 157

    // A: y = x @ W_in2f
    gemm128_kernel<<<gridAC, 256, SMEM_AC>>>(x, W_in2f, nullptr, ybuf, 0);
    // B: fused filter net + gather + reduce -> acc
    cfconv_main_kernel<<<GRID_B, 256, SMEM_B>>>(dR, dRe, pmask, nbr, W1, b1, W2, b2);
    // C: out = ssp(acc @ W_f2out + b_f2out)
    gemm128_kernel<<<gridAC, 256, SMEM_AC>>>(accb, W_f2out, b_f2out, out, 1);
}

// round 2
// speedup vs baseline: 1.0514x; 1.0514x over previous
#include <cuda_runtime.h>

#define NATOMS 10000
#define NNBH   48
#define NIN    128
#define NF     128
#define NOUT   128
#define NG     25
#define RCUT   5.0f
#define LN2F   0.69314718055994531f

typedef unsigned long long u64;

// scratch (allocation-free rule: device globals)
__device__ __align__(16) float g_ybuf[NATOMS * NF];
__device__ __align__(16) float g_acc [NATOMS * NF];

__device__ __forceinline__ float sspf(float v) {
    float e  = __expf(-fabsf(v));
    float sp = fmaxf(v, 0.0f) + __logf(1.0f + e);
    return sp - LN2F;
}

// ---- packed f32x2 helpers (Blackwell double-rate FP32) ----
__device__ __forceinline__ u64 pk2(float lo, float hi) {
    u64 r; asm("mov.b64 %0, {%1, %2};" : "=l"(r) : "f"(lo), "f"(hi)); return r;
}
__device__ __forceinline__ void ffma2(u64& d, u64 a, u64 b) {
    asm("fma.rn.f32x2 %0, %1, %2, %0;" : "+l"(d) : "l"(a), "l"(b));
}
__device__ __forceinline__ u64 mul2(u64 a, u64 b) {
    u64 r; asm("mul.rn.f32x2 %0, %1, %2;" : "=l"(r) : "l"(a), "l"(b)); return r;
}
__device__ __forceinline__ float2 up2(u64 v) {
    float2 f; asm("mov.b64 {%0, %1}, %2;" : "=f"(f.x), "=f"(f.y) : "l"(v)); return f;
}

// ---------------------------------------------------------------------------
// Kernel A/C: 64x128 tile GEMM, depth 128. micro-tile 4x8, 256 threads, f32x2.
//   mode 0: out = X @ W              (kernel A: in2f)
//   mode 1: out = ssp(X @ W + bias)  (kernel C: f2out)
// ---------------------------------------------------------------------------
__global__ __launch_bounds__(256) void gemm128_kernel(
    const float* __restrict__ X, const float* __restrict__ W,
    const float* __restrict__ bias, float* __restrict__ out, int mode)
{
    extern __shared__ float smem[];
    float* sW = smem;            // 16384
    float* sX = smem + 16384;    // 8192

    int tid = threadIdx.x;
    const float4* Wv = (const float4*)W;
    float4* sWv = (float4*)sW;
    #pragma unroll
    for (int i = 0; i < 16; i++) sWv[tid + i * 256] = Wv[tid + i * 256];

    int row0 = blockIdx.x * 64;
    const float4* Xv = (const float4*)X;
    float4* sXv = (float4*)sX;
    #pragma unroll
    for (int i = 0; i < 8; i++) {
        int idx = tid + i * 256;
        int r = idx >> 5, c4 = idx & 31;
        float4 v = make_float4(0.f, 0.f, 0.f, 0.f);
        if (row0 + r < NATOMS) v = Xv[(size_t)(row0 + r) * 32 + c4];
        sXv[idx] = v;
    }
    __syncthreads();

    int tr = tid >> 4, tc = tid & 15;
    int r0 = tr * 4, c0 = tc * 8;

    u64 acc[4][4];
    #pragma unroll
    for (int i = 0; i < 4; i++)
        #pragma unroll
        for (int p = 0; p < 4; p++) acc[i][p] = 0ull;

    #pragma unroll 2
    for (int j = 0; j < NIN; j += 4) {
        float4 a0 = *(float4*)&sX[(r0 + 0) * NIN + j];
        float4 a1 = *(float4*)&sX[(r0 + 1) * NIN + j];
        float4 a2 = *(float4*)&sX[(r0 + 2) * NIN + j];
        float4 a3 = *(float4*)&sX[(r0 + 3) * NIN + j];
        const float* af0 = (const float*)&a0;
        const float* af1 = (const float*)&a1;
        const float* af2 = (const float*)&a2;
        const float* af3 = (const float*)&a3;
        #pragma unroll
        for (int jj = 0; jj < 4; jj++) {
            ulonglong2 w0 = *(ulonglong2*)&sW[(j + jj) * NF + c0];
            ulonglong2 w1 = *(ulonglong2*)&sW[(j + jj) * NF + c0 + 4];
            u64 p0 = pk2(af0[jj], af0[jj]);
            u64 p1 = pk2(af1[jj], af1[jj]);
            u64 p2 = pk2(af2[jj], af2[jj]);
            u64 p3 = pk2(af3[jj], af3[jj]);
            ffma2(acc[0][0], p0, w0.x); ffma2(acc[0][1], p0, w0.y);
            ffma2(acc[0][2], p0, w1.x); ffma2(acc[0][3], p0, w1.y);
            ffma2(acc[1][0], p1, w0.x); ffma2(acc[1][1], p1, w0.y);
            ffma2(acc[1][2], p1, w1.x); ffma2(acc[1][3], p1, w1.y);
            ffma2(acc[2][0], p2, w0.x); ffma2(acc[2][1], p2, w0.y);
            ffma2(acc[2][2], p2, w1.x); ffma2(acc[2][3], p2, w1.y);
            ffma2(acc[3][0], p3, w0.x); ffma2(acc[3][1], p3, w0.y);
            ffma2(acc[3][2], p3, w1.x); ffma2(acc[3][3], p3, w1.y);
        }
    }

    float bb[8];
    if (mode == 1) {
        #pragma unroll
        for (int c = 0; c < 8; c++) bb[c] = bias[c0 + c];
    }
    #pragma unroll
    for (int i = 0; i < 4; i++) {
        int r = row0 + r0 + i;
        if (r < NATOMS) {
            float o[8];
            #pragma unroll
            for (int p = 0; p < 4; p++) {
                float2 f = up2(acc[i][p]);
                o[2 * p] = f.x; o[2 * p + 1] = f.y;
            }
            if (mode == 1) {
                #pragma unroll
                for (int c = 0; c < 8; c++) o[c] = sspf(o[c] + bb[c]);
            }
            *(float4*)&out[(size_t)r * NF + c0]     = make_float4(o[0], o[1], o[2], o[3]);
            *(float4*)&out[(size_t)r * NF + c0 + 4] = make_float4(o[4], o[5], o[6], o[7]);
        }
    }
}

// ---------------------------------------------------------------------------
// Kernel B: fused filter-network + cutoff + gather + K-reduction (f32x2).
// ---------------------------------------------------------------------------
#define GRID_B 1216

__global__ __launch_bounds__(256, 1) void cfconv_main_kernel(
    const float* __restrict__ dR,   const float* __restrict__ dRe,
    const float* __restrict__ pmask,const int*   __restrict__ nbr,
    const float* __restrict__ W1,   const float* __restrict__ b1,
    const float* __restrict__ W2,   const float* __restrict__ b2)
{
    extern __shared__ float smem[];
    float* sW2  = smem;                 // 16384
    float* sW1  = sW2 + 16384;          // 3200
    float* sH   = sW1 + 3200;           // 6144
    float* sG   = sH  + 6144;           // 1200
    float* sRed = sG  + 1200;           // 2048
    float* sCM  = sRed + 2048;          // 48
    int*   sIdx = (int*)(sCM + 48);     // 48

    int tid = threadIdx.x;

    #pragma unroll
    for (int i = tid; i < NG * NF; i += 256) sW1[i] = W1[i];
    {
        const float4* w2v = (const float4*)W2;
        float4* sw2v = (float4*)sW2;
        #pragma unroll
        for (int i = 0; i < 16; i++) sw2v[tid + i * 256] = w2v[tid + i * 256];
    }

    int tr = tid >> 4, tc = tid & 15;
    int r0 = tr * 3, c0 = tc * 8;

    u64 b1p[4], b2p[4];
    #pragma unroll
    for (int p = 0; p < 4; p++) {
        b1p[p] = pk2(b1[c0 + 2 * p], b1[c0 + 2 * p + 1]);
        b2p[p] = pk2(b2[c0 + 2 * p], b2[c0 + 2 * p + 1]);
    }

    for (int atom = blockIdx.x; atom < NATOMS; atom += GRID_B) {
        __syncthreads();  // A: previous iteration fully consumed shared state

        const float* gsrc = dRe + (size_t)atom * (NNBH * NG);
        #pragma unroll
        for (int i = tid; i < NNBH * NG; i += 256) sG[i] = gsrc[i];
        if (tid < NNBH) {
            sIdx[tid] = nbr[(size_t)atom * NNBH + tid];
            float d = dR[(size_t)atom * NNBH + tid];
            sCM[tid] = (d <= RCUT ? 1.0f : 0.0f) * pmask[(size_t)atom * NNBH + tid];
        }
        __syncthreads();  // B: inputs visible

        // GEMM1: H = ssp(G @ W1 + b1)
        {
            u64 h[3][4];
            #pragma unroll
            for (int i = 0; i < 3; i++)
                #pragma unroll
                for (int p = 0; p < 4; p++) h[i][p] = b1p[p];
            #pragma unroll
            for (int g = 0; g < NG; g++) {
                float a0 = sG[(r0 + 0) * NG + g];
                float a1 = sG[(r0 + 1) * NG + g];
                float a2 = sG[(r0 + 2) * NG + g];
                ulonglong2 w0 = *(ulonglong2*)&sW1[g * NF + c0];
                ulonglong2 w1 = *(ulonglong2*)&sW1[g * NF + c0 + 4];
                u64 p0 = pk2(a0, a0), p1 = pk2(a1, a1), p2 = pk2(a2, a2);
                ffma2(h[0][0], p0, w0.x); ffma2(h[0][1], p0, w0.y);
                ffma2(h[0][2], p0, w1.x); ffma2(h[0][3], p0, w1.y);
                ffma2(h[1][0], p1, w0.x); ffma2(h[1][1], p1, w0.y);
                ffma2(h[1][2], p1, w1.x); ffma2(h[1][3], p1, w1.y);
                ffma2(h[2][0], p2, w0.x); ffma2(h[2][1], p2, w0.y);
                ffma2(h[2][2], p2, w1.x); ffma2(h[2][3], p2, w1.y);
            }
            #pragma unroll
            for (int i = 0; i < 3; i++) {
                float o[8];
                #pragma unroll
                for (int p = 0; p < 4; p++) {
                    float2 f = up2(h[i][p]);
                    o[2 * p] = sspf(f.x); o[2 * p + 1] = sspf(f.y);
                }
                *(float4*)&sH[(r0 + i) * NF + c0]     = make_float4(o[0], o[1], o[2], o[3]);
                *(float4*)&sH[(r0 + i) * NF + c0 + 4] = make_float4(o[4], o[5], o[6], o[7]);
            }
        }
        __syncthreads();  // C: H visible

        // GEMM2: P = H @ W2 + b2
        u64 acc[3][4];
        #pragma unroll
        for (int i = 0; i < 3; i++)
            #pragma unroll
            for (int p = 0; p < 4; p++) acc[i][p] = b2p[p];

        #pragma unroll 2
        for (int j = 0; j < NF; j += 4) {
            float4 a0 = *(float4*)&sH[(r0 + 0) * NF + j];
            float4 a1 = *(float4*)&sH[(r0 + 1) * NF + j];
            float4 a2 = *(float4*)&sH[(r0 + 2) * NF + j];
            const float* af0 = (const float*)&a0;
            const float* af1 = (const float*)&a1;
            const float* af2 = (const float*)&a2;
            #pragma unroll
            for (int jj = 0; jj < 4; jj++) {
                ulonglong2 w0 = *(ulonglong2*)&sW2[(j + jj) * NF + c0];
                ulonglong2 w1 = *(ulonglong2*)&sW2[(j + jj) * NF + c0 + 4];
                u64 p0 = pk2(af0[jj], af0[jj]);
                u64 p1 = pk2(af1[jj], af1[jj]);
                u64 p2 = pk2(af2[jj], af2[jj]);
                ffma2(acc[0][0], p0, w0.x); ffma2(acc[0][1], p0, w0.y);
                ffma2(acc[0][2], p0, w1.x); ffma2(acc[0][3], p0, w1.y);
                ffma2(acc[1][0], p1, w0.x); ffma2(acc[1][1], p1, w0.y);
                ffma2(acc[1][2], p1, w1.x); ffma2(acc[1][3], p1, w1.y);
                ffma2(acc[2][0], p2, w0.x); ffma2(acc[2][1], p2, w0.y);
                ffma2(acc[2][2], p2, w1.x); ffma2(acc[2][3], p2, w1.y);
            }
        }

        // epilogue: cutoff*mask, gather y[idx], partial reduce over rows
        u64 part[4];
        #pragma unroll
        for (int p = 0; p < 4; p++) part[p] = 0ull;
        #pragma unroll
        for (int i = 0; i < 3; i++) {
            int k = r0 + i;
            float cm = sCM[k];
            u64 cm2 = pk2(cm, cm);
            const float* yrow = g_ybuf + (size_t)sIdx[k] * NF + c0;
            ulonglong2 y0 = *(const ulonglong2*)yrow;
            ulonglong2 y1 = *(const ulonglong2*)(yrow + 4);
            ffma2(part[0], mul2(acc[i][0], y0.x), cm2);
            ffma2(part[1], mul2(acc[i][1], y0.y), cm2);
            ffma2(part[2], mul2(acc[i][2], y1.x), cm2);
            ffma2(part[3], mul2(acc[i][3], y1.y), cm2);
        }
        *(ulonglong2*)&sRed[tr * NF + c0]     = make_ulonglong2(part[0], part[1]);
        *(ulonglong2*)&sRed[tr * NF + c0 + 4] = make_ulonglong2(part[2], part[3]);
        __syncthreads();  // D: partials visible

        if (tid < NF) {
            float s = 0.f;
            #pragma unroll
            for (int t = 0; t < 16; t++) s += sRed[t * NF + tid];
            g_acc[(size_t)atom * NF + tid] = s;
        }
    }
}

// ---------------------------------------------------------------------------
extern "C" void kernel_launch(void* const* d_in, const int* in_sizes, int n_in,
                              void* d_out, int out_size)
{
    const float* x       = (const float*)d_in[0];
    const float* dR      = (const float*)d_in[1];
    const float* dRe     = (const float*)d_in[2];
    const float* pmask   = (const float*)d_in[3];
    const int*   nbr     = (const int*)  d_in[4];
    const float* W1      = (const float*)d_in[5];
    const float* b1      = (const float*)d_in[6];
    const float* W2      = (const float*)d_in[7];
    const float* b2      = (const float*)d_in[8];
    const float* W_in2f  = (const float*)d_in[9];
    const float* W_f2out = (const float*)d_in[10];
    const float* b_f2out = (const float*)d_in[11];
    float* out = (float*)d_out;

    const int SMEM_AC = (16384 + 64 * 128) * 4;
    const int SMEM_B  = (16384 + 3200 + 6144 + 1200 + 2048 + 48) * 4 + 48 * 4;

    cudaFuncSetAttribute(gemm128_kernel,     cudaFuncAttributeMaxDynamicSharedMemorySize, SMEM_AC);
    cudaFuncSetAttribute(cfconv_main_kernel, cudaFuncAttributeMaxDynamicSharedMemorySize, SMEM_B);

    float* ybuf; cudaGetSymbolAddress((void**)&ybuf, g_ybuf);
    float* accb; cudaGetSymbolAddress((void**)&accb, g_acc);

    int gridAC = (NATOMS + 63) / 64;  // 157

    gemm128_kernel<<<gridAC, 256, SMEM_AC>>>(x, W_in2f, nullptr, ybuf, 0);
    cfconv_main_kernel<<<GRID_B, 256, SMEM_B>>>(dR, dRe, pmask, nbr, W1, b1, W2, b2);
    gemm128_kernel<<<gridAC, 256, SMEM_AC>>>(accb, W_f2out, b_f2out, out, 1);
}